// round 8
// baseline (speedup 1.0000x reference)
#include <cuda_runtime.h>
#include <cuda_bf16.h>
#include <cstdint>

// Problem constants
#define NN 16384
#define DD 1024
#define CC 1024
#define EPSV 1e-6f
#define DEN_EPS 1e-5f

#define NPREP 64           // producer CTAs (bids 0..63, wave-1 resident)
#define NGTILES 1024       // 128 row-blocks x 8 col-blocks

// ---------------- device scratch ---------------------------------------------
__device__ __align__(1024) __nv_bfloat16 g_fb[NN * DD];   // features bf16 (32MB)
__device__ __align__(1024) __nv_bfloat16 g_cb[CC * DD];   // centers  bf16 ( 2MB)
__device__ float g_rowterm[NN];
__device__ float g_centerterm[CC];
__device__ int   g_minmap[NN];
__device__ int   g_gcnt[128];       // per-128-row-group completion counters
__device__ int   g_cdone;           // center rows completed (target 1024)
__device__ int   g_odd_nonzero;

// ---------------- helpers -------------------------------------------------------
__device__ __forceinline__ int fmap(float f) {
    int i = __float_as_int(f);
    return i >= 0 ? i : (i ^ 0x7FFFFFFF);
}
__device__ __forceinline__ float funmap(int i) {
    return __int_as_float(i >= 0 ? i : (i ^ 0x7FFFFFFF));
}

__device__ __forceinline__ void cp16(void* dst, const void* src) {
    unsigned d = (unsigned)__cvta_generic_to_shared(dst);
    asm volatile("cp.async.cg.shared.global [%0], [%1], 16;\n" :: "r"(d), "l"(src) : "memory");
}
__device__ __forceinline__ void cp_commit() {
    asm volatile("cp.async.commit_group;\n" ::: "memory");
}
template <int N>
__device__ __forceinline__ void cp_wait() {
    asm volatile("cp.async.wait_group %0;\n" :: "n"(N) : "memory");
}

__device__ __forceinline__ void ldm_x4(uint32_t* r, uint32_t saddr) {
    asm volatile("ldmatrix.sync.aligned.m8n8.x4.shared.b16 {%0,%1,%2,%3}, [%4];\n"
                 : "=r"(r[0]), "=r"(r[1]), "=r"(r[2]), "=r"(r[3]) : "r"(saddr));
}

__device__ __forceinline__ void mma16816(float* c, const uint32_t* a,
                                         uint32_t b0, uint32_t b1) {
    asm volatile(
        "mma.sync.aligned.m16n8k16.row.col.f32.bf16.bf16.f32 "
        "{%0,%1,%2,%3}, {%4,%5,%6,%7}, {%8,%9}, {%0,%1,%2,%3};\n"
        : "+f"(c[0]), "+f"(c[1]), "+f"(c[2]), "+f"(c[3])
        : "r"(a[0]), "r"(a[1]), "r"(a[2]), "r"(a[3]), "r"(b0), "r"(b1));
}

// ---------------- per-warp row conversion (fp32 -> bf16 + term) ------------------
// One warp converts one row of D=1024 floats. Returns after all lane stores issued.
__device__ __forceinline__ void conv_row_warp(const float* __restrict__ src,
                                              __nv_bfloat16* dst, float* term,
                                              int row, float coef, float add) {
    int lane = threadIdx.x & 31;
    const float4* s4 = reinterpret_cast<const float4*>(src + (size_t)row * DD);
    uint2* d2 = reinterpret_cast<uint2*>(dst + (size_t)row * DD);

    float s = 0.f, s2 = 0.f;
    #pragma unroll
    for (int i = 0; i < 8; i++) {
        float4 v = s4[i * 32 + lane];
        __nv_bfloat162 lo = __floats2bfloat162_rn(v.x, v.y);
        __nv_bfloat162 hi = __floats2bfloat162_rn(v.z, v.w);
        uint2 packed;
        packed.x = *reinterpret_cast<uint32_t*>(&lo);
        packed.y = *reinterpret_cast<uint32_t*>(&hi);
        d2[i * 32 + lane] = packed;
        s  += v.x + v.y + v.z + v.w;
        s2 += v.x * v.x + v.y * v.y + v.z * v.z + v.w * v.w;
    }
    #pragma unroll
    for (int off = 16; off; off >>= 1) {
        s  += __shfl_xor_sync(0xffffffff, s,  off);
        s2 += __shfl_xor_sync(0xffffffff, s2, off);
    }
    if (lane == 0) term[row] = s2 + coef * s + add;
}

// ---------------- flag init (re-zeroed every replay) ------------------------------
__global__ void init_flags() {
    int t = threadIdx.x;
    if (t < 128) g_gcnt[t] = 0;
    if (t == 128) g_cdone = 0;
    if (t == 129) g_odd_nonzero = 0;
}

// ---------------- fused producer/consumer kernel ----------------------------------
// bids [0,64): producers (centers then features, strided rows, flag per row).
// bids [64,1088): one 128x128 GEMM tile each; spin on flags, then R6 mainloop.
#define BM 128
#define BN 128
#define BK 64
#define NK (DD / BK)            // 16
#define A_BYTES (BM * BK * 2)   // 16384
#define B_BYTES (BN * BK * 2)   // 16384
#define STAGE_BYTES (A_BYTES + B_BYTES)
#define STAGES 3
#define GEMM_SMEM (STAGES * STAGE_BYTES + 16)
#define NTHREADS 128

// swizzled byte offset for (row, kbyte) — loader-side (not hot)
__device__ __forceinline__ uint32_t swz(int r, int kbyte) {
    return (uint32_t)(r * 128 + (((kbyte >> 4) ^ (r & 7)) << 4) + (kbyte & 15));
}

__global__ void __launch_bounds__(NTHREADS, 2) fused_kernel(
        const float* __restrict__ f, const float* __restrict__ c,
        const unsigned int* __restrict__ lw) {
    extern __shared__ char sm_raw[];
    const int tid  = threadIdx.x;
    const int lane = tid & 31;
    const int wrp  = tid >> 5;       // 0..3
    const int bid  = blockIdx.x;

    if (bid < NPREP) {
        // ---- labels dtype detect: words [bid*256, bid*256+256) ----
        #pragma unroll
        for (int i = 0; i < 2; i++) {
            int idx = bid * 256 + tid + i * 128;      // < 16384
            if ((idx & 1) && lw[idx] != 0u) atomicOr(&g_odd_nonzero, 1);
        }

        // ---- centers: 16 rows per CTA, 4 per warp ----
        #pragma unroll
        for (int jj = 0; jj < 4; jj++) {
            int row = bid * 16 + wrp * 4 + jj;        // < 1024
            conv_row_warp(c, g_cb, g_centerterm, row, -2.0f * EPSV, 0.0f);
            __threadfence();
            __syncwarp();
            if (lane == 0) atomicAdd(&g_cdone, 1);
        }

        // ---- features: 64 rows per warp, global stride 64, ascending ----
        for (int j = 0; j < 32; j++) {
            #pragma unroll
            for (int h = 0; h < 2; h++) {
                int r = bid + 64 * (8 * j + 2 * wrp + h);   // < 16384
                conv_row_warp(f, g_fb, g_rowterm, r,
                              2.0f * EPSV, EPSV * EPSV * (float)DD);
                if (lane == 0) g_minmap[r] = 0x7F800000;    // fmap(+inf)
                __threadfence();
                __syncwarp();
                if (lane == 0) atomicAdd(&g_gcnt[r >> 7], 1);
            }
        }
        return;
    }

    // =========================== GEMM consumer ====================================
    const int tile    = bid - NPREP;
    const int row_blk = tile >> 3;
    const int brow    = row_blk * BM;
    const int bcol    = (tile & 7) * BN;
    const int wm      = wrp >> 1;    // 0..1
    const int wn      = wrp & 1;     // 0..1

    // wait for centers + this row group (acquire)
    if (tid == 0) {
        volatile int* cd = &g_cdone;
        while (*cd < 1024) __nanosleep(128);
        volatile int* gc = &g_gcnt[row_blk];
        while (*gc < 128) __nanosleep(128);
        __threadfence();
    }
    __syncthreads();

    char* smb = sm_raw;
    const __nv_bfloat16* Ag = g_fb + (size_t)brow * DD;
    const __nv_bfloat16* Bg = g_cb + (size_t)bcol * DD;
    const uint32_t smem0 = (uint32_t)__cvta_generic_to_shared(smb);

    // XOR-folded LDSM base offsets
    uint32_t aB[4], bB[4];
    {
        uint32_t hi16 = ((lane >> 4) & 1) << 4;
        #pragma unroll
        for (int mt = 0; mt < 4; mt++) {
            int r = wm * 64 + mt * 16 + (lane & 15);
            aB[mt] = ((uint32_t)(r * 128) | (uint32_t)((r & 7) << 4)) ^ hi16;
        }
        uint32_t hib = ((lane >> 3) & 1) << 4;
        #pragma unroll
        for (int p = 0; p < 4; p++) {
            int r = wn * 64 + p * 16 + (lane & 7) + ((lane & 16) >> 1);
            bB[p] = ((uint32_t)(r * 128) | (uint32_t)((r & 7) << 4)) ^ hib;
        }
    }

    float acc[4][8][4];
    #pragma unroll
    for (int mt = 0; mt < 4; mt++)
        #pragma unroll
        for (int nt = 0; nt < 8; nt++)
            #pragma unroll
            for (int j = 0; j < 4; j++) acc[mt][nt][j] = 0.f;

    auto stage = [&](int kt, int buf) {
        int k0 = kt * BK;
        char* As = smb + buf * STAGE_BYTES;
        char* Bs = As + A_BYTES;
        #pragma unroll
        for (int i = 0; i < 8; i++) {
            int idx = tid + i * NTHREADS;
            int r = idx >> 3, cc2 = idx & 7;
            cp16(As + swz(r, cc2 * 16), Ag + (size_t)r * DD + k0 + cc2 * 8);
        }
        #pragma unroll
        for (int i = 0; i < 8; i++) {
            int idx = tid + i * NTHREADS;
            int r = idx >> 3, cc2 = idx & 7;
            cp16(Bs + swz(r, cc2 * 16), Bg + (size_t)r * DD + k0 + cc2 * 8);
        }
        cp_commit();
    };

    stage(0, 0);
    stage(1, 1);

    for (int kt = 0; kt < NK; kt++) {
        if (kt < NK - 1) cp_wait<1>(); else cp_wait<0>();
        __syncthreads();

        const uint32_t a_base = smem0 + (uint32_t)((kt % STAGES) * STAGE_BYTES);
        const uint32_t b_base = a_base + A_BYTES;

        // ks = 0: LDSMs first so the tensor pipe refills right after the barrier
        uint32_t a[4][4], b[4][4];
        #pragma unroll
        for (int mt = 0; mt < 4; mt++) ldm_x4(a[mt], a_base + aB[mt]);
        #pragma unroll
        for (int p = 0; p < 4; p++)  ldm_x4(b[p],  b_base + bB[p]);

        if (kt + 2 < NK) stage(kt + 2, (kt + 2) % STAGES);

        #pragma unroll
        for (int mt = 0; mt < 4; mt++)
            #pragma unroll
            for (int p = 0; p < 4; p++) {
                mma16816(acc[mt][2 * p],     a[mt], b[p][0], b[p][1]);
                mma16816(acc[mt][2 * p + 1], a[mt], b[p][2], b[p][3]);
            }

        #pragma unroll
        for (int ks = 1; ks < 4; ks++) {
            const uint32_t kx = (uint32_t)(ks * 32);
            #pragma unroll
            for (int mt = 0; mt < 4; mt++) ldm_x4(a[mt], a_base + (aB[mt] ^ kx));
            #pragma unroll
            for (int p = 0; p < 4; p++)  ldm_x4(b[p],  b_base + (bB[p] ^ kx));
            #pragma unroll
            for (int mt = 0; mt < 4; mt++)
                #pragma unroll
                for (int p = 0; p < 4; p++) {
                    mma16816(acc[mt][2 * p],     a[mt], b[p][0], b[p][1]);
                    mma16816(acc[mt][2 * p + 1], a[mt], b[p][2], b[p][3]);
                }
        }
    }

    // ---- fused min epilogue ----
    const float* ctp = g_centerterm + bcol + wn * 64 + (lane & 3) * 2;
    float ct0[8], ct1[8];
    #pragma unroll
    for (int nt = 0; nt < 8; nt++) {
        ct0[nt] = __ldg(ctp + nt * 8);
        ct1[nt] = __ldg(ctp + nt * 8 + 1);
    }
    #pragma unroll
    for (int mt = 0; mt < 4; mt++) {
        float m0 = 1e30f, m1 = 1e30f;
        #pragma unroll
        for (int nt = 0; nt < 8; nt++) {
            m0 = fminf(m0, fminf(fmaf(-2.f, acc[mt][nt][0], ct0[nt]),
                                 fmaf(-2.f, acc[mt][nt][1], ct1[nt])));
            m1 = fminf(m1, fminf(fmaf(-2.f, acc[mt][nt][2], ct0[nt]),
                                 fmaf(-2.f, acc[mt][nt][3], ct1[nt])));
        }
        #pragma unroll
        for (int off = 1; off < 4; off <<= 1) {
            m0 = fminf(m0, __shfl_xor_sync(0xffffffff, m0, off));
            m1 = fminf(m1, __shfl_xor_sync(0xffffffff, m1, off));
        }
        if ((lane & 3) == 0) {
            int r = brow + wm * 64 + mt * 16 + (lane >> 2);
            atomicMin(&g_minmap[r],     fmap(m0));
            atomicMin(&g_minmap[r + 8], fmap(m1));
        }
    }
}

// ---------------- fused masked reduction (single block) ---------------------------
__global__ void __launch_bounds__(1024) reduce_final_kernel(
        const void* __restrict__ labels, float* __restrict__ out) {
    int tid = threadIdx.x;
    bool lab64 = (g_odd_nonzero == 0);

    float s = 0.f, c = 0.f;
    #pragma unroll
    for (int i = 0; i < 16; i++) {
        int row = tid + i * 1024;
        float m    = funmap(g_minmap[row]);
        float sq   = g_rowterm[row] + m;
        float dist = sqrtf(fmaxf(sq, 0.f));
        long long lab = lab64 ? ((const long long*)labels)[row]
                              : (long long)((const int*)labels)[row];
        if (lab == 0) { s += dist; c += 1.f; }
    }
    #pragma unroll
    for (int off = 16; off; off >>= 1) {
        s += __shfl_xor_sync(0xffffffff, s, off);
        c += __shfl_xor_sync(0xffffffff, c, off);
    }
    __shared__ float sh[2][32];
    int w = tid >> 5, l = tid & 31;
    if (l == 0) { sh[0][w] = s; sh[1][w] = c; }
    __syncthreads();
    if (w == 0) {
        float ts = sh[0][l], tc = sh[1][l];
        #pragma unroll
        for (int off = 16; off; off >>= 1) {
            ts += __shfl_xor_sync(0xffffffff, ts, off);
            tc += __shfl_xor_sync(0xffffffff, tc, off);
        }
        if (l == 0) out[0] = ts / (tc + DEN_EPS);
    }
}

// ---------------- launch -------------------------------------------------------------
extern "C" void kernel_launch(void* const* d_in, const int* in_sizes, int n_in,
                              void* d_out, int out_size) {
    const float* features = (const float*)d_in[0];
    const void*  labels   = d_in[1];
    const float* centers  = (const float*)d_in[2];
    float* out = (float*)d_out;

    cudaFuncSetAttribute(fused_kernel,
                         cudaFuncAttributeMaxDynamicSharedMemorySize, GEMM_SMEM);

    init_flags<<<1, 256>>>();
    fused_kernel<<<NPREP + NGTILES, NTHREADS, GEMM_SMEM>>>(
        features, centers, (const unsigned int*)labels);
    reduce_final_kernel<<<1, 1024>>>(labels, out);
}

// round 9
// speedup vs baseline: 1.3129x; 1.3129x over previous
#include <cuda_runtime.h>
#include <cuda_bf16.h>
#include <cstdint>

// Problem constants
#define NN 16384
#define DD 1024
#define CC 1024
#define EPSV 1e-6f
#define DEN_EPS 1e-5f

// ---------------- device scratch (zero-init at module load) ---------------------
__device__ __align__(1024) __nv_bfloat16 g_fb[NN * DD];   // features bf16 (32MB)
__device__ __align__(1024) __nv_bfloat16 g_cb[CC * DD];   // centers  bf16 ( 2MB)
__device__ float g_rowterm[NN];
__device__ float g_centerterm[CC];
__device__ int   g_minmap[NN];
__device__ int   g_gcnt[128];   // per-128-row-group counters (re-zeroed by reduce_final)
__device__ int   g_cdone;      // center rows done (target 1024, re-zeroed by reduce_final)

// ---------------- helpers ---------------------------------------------------------
__device__ __forceinline__ int fmap(float f) {
    int i = __float_as_int(f);
    return i >= 0 ? i : (i ^ 0x7FFFFFFF);
}
__device__ __forceinline__ float funmap(int i) {
    return __int_as_float(i >= 0 ? i : (i ^ 0x7FFFFFFF));
}

__device__ __forceinline__ void cp16(void* dst, const void* src) {
    unsigned d = (unsigned)__cvta_generic_to_shared(dst);
    asm volatile("cp.async.cg.shared.global [%0], [%1], 16;\n" :: "r"(d), "l"(src) : "memory");
}
__device__ __forceinline__ void cp_commit() {
    asm volatile("cp.async.commit_group;\n" ::: "memory");
}
template <int N>
__device__ __forceinline__ void cp_wait() {
    asm volatile("cp.async.wait_group %0;\n" :: "n"(N) : "memory");
}

__device__ __forceinline__ void ldm_x4(uint32_t* r, uint32_t saddr) {
    asm volatile("ldmatrix.sync.aligned.m8n8.x4.shared.b16 {%0,%1,%2,%3}, [%4];\n"
                 : "=r"(r[0]), "=r"(r[1]), "=r"(r[2]), "=r"(r[3]) : "r"(saddr));
}

__device__ __forceinline__ void mma16816(float* c, const uint32_t* a,
                                         uint32_t b0, uint32_t b1) {
    asm volatile(
        "mma.sync.aligned.m16n8k16.row.col.f32.bf16.bf16.f32 "
        "{%0,%1,%2,%3}, {%4,%5,%6,%7}, {%8,%9}, {%0,%1,%2,%3};\n"
        : "+f"(c[0]), "+f"(c[1]), "+f"(c[2]), "+f"(c[3])
        : "r"(a[0]), "r"(a[1]), "r"(a[2]), "r"(a[3]), "r"(b0), "r"(b1));
}

// ---------------- warp converts ONE row -------------------------------------------
__device__ __forceinline__ void conv_row1(const float* __restrict__ src,
                                          __nv_bfloat16* dst, float* term,
                                          int row, float coef, float add) {
    const int lane = threadIdx.x & 31;
    const float4* s4 = reinterpret_cast<const float4*>(src + (size_t)row * DD);
    uint2* d2 = reinterpret_cast<uint2*>(dst + (size_t)row * DD);
    float s = 0.f, s2 = 0.f;
    #pragma unroll
    for (int i = 0; i < 8; i++) {
        float4 v = s4[i * 32 + lane];
        __nv_bfloat162 lo = __floats2bfloat162_rn(v.x, v.y);
        __nv_bfloat162 hi = __floats2bfloat162_rn(v.z, v.w);
        uint2 packed;
        packed.x = *reinterpret_cast<uint32_t*>(&lo);
        packed.y = *reinterpret_cast<uint32_t*>(&hi);
        d2[i * 32 + lane] = packed;
        s  += v.x + v.y + v.z + v.w;
        s2 += v.x * v.x + v.y * v.y + v.z * v.z + v.w * v.w;
    }
    #pragma unroll
    for (int off = 16; off; off >>= 1) {
        s  += __shfl_xor_sync(0xffffffff, s,  off);
        s2 += __shfl_xor_sync(0xffffffff, s2, off);
    }
    if (lane == 0) term[row] = s2 + coef * s + add;
}

// ---------------- warp converts 4 consecutive rows (interleaved for MLP) ----------
__device__ __forceinline__ void conv_rows4(const float* __restrict__ src,
                                           __nv_bfloat16* dst, float* term,
                                           int row0, float coef, float add) {
    const int lane = threadIdx.x & 31;
    const float4* s4 = reinterpret_cast<const float4*>(src + (size_t)row0 * DD);
    uint2* d2 = reinterpret_cast<uint2*>(dst + (size_t)row0 * DD);

    float s[4]  = {0.f, 0.f, 0.f, 0.f};
    float s2[4] = {0.f, 0.f, 0.f, 0.f};
    #pragma unroll
    for (int i = 0; i < 8; i++) {
        float4 v[4];
        #pragma unroll
        for (int rr = 0; rr < 4; rr++) v[rr] = s4[rr * 256 + i * 32 + lane];
        #pragma unroll
        for (int rr = 0; rr < 4; rr++) {
            __nv_bfloat162 lo = __floats2bfloat162_rn(v[rr].x, v[rr].y);
            __nv_bfloat162 hi = __floats2bfloat162_rn(v[rr].z, v[rr].w);
            uint2 packed;
            packed.x = *reinterpret_cast<uint32_t*>(&lo);
            packed.y = *reinterpret_cast<uint32_t*>(&hi);
            d2[rr * 256 + i * 32 + lane] = packed;
            s[rr]  += v[rr].x + v[rr].y + v[rr].z + v[rr].w;
            s2[rr] += v[rr].x * v[rr].x + v[rr].y * v[rr].y
                    + v[rr].z * v[rr].z + v[rr].w * v[rr].w;
        }
    }
    #pragma unroll
    for (int rr = 0; rr < 4; rr++) {
        #pragma unroll
        for (int off = 16; off; off >>= 1) {
            s[rr]  += __shfl_xor_sync(0xffffffff, s[rr],  off);
            s2[rr] += __shfl_xor_sync(0xffffffff, s2[rr], off);
        }
        if (lane == 0) term[row0 + rr] = s2[rr] + coef * s[rr] + add;
    }
}

// ---------------- fused convert + GEMM + min epilogue -----------------------------
#define BM 128
#define BN 128
#define BK 64
#define NK (DD / BK)            // 16
#define A_BYTES (BM * BK * 2)   // 16384
#define B_BYTES (BN * BK * 2)   // 16384
#define STAGE_BYTES (A_BYTES + B_BYTES)
#define STAGES 3
#define GEMM_SMEM (STAGES * STAGE_BYTES + 16)
#define NTHREADS 128
#define NGTILES 1024

__device__ __forceinline__ uint32_t swz(int r, int kbyte) {
    return (uint32_t)(r * 128 + (((kbyte >> 4) ^ (r & 7)) << 4) + (kbyte & 15));
}

__global__ void __launch_bounds__(NTHREADS, 2) fused_kernel(
        const float* __restrict__ f, const float* __restrict__ c) {
    extern __shared__ char sm_raw[];
    const int tid  = threadIdx.x;
    const int lane = tid & 31;
    const int wrp  = tid >> 5;       // 0..3
    const int bid  = blockIdx.x;

    const int row_blk = bid >> 3;
    const int brow    = row_blk * BM;
    const int bcol    = (bid & 7) * BN;
    const int wm      = wrp >> 1;    // 0..1
    const int wn      = wrp & 1;     // 0..1

    // ---- centers: bids 0..255 convert 4 rows each (1 per warp), wave-1 resident ----
    if (bid < 256) {
        conv_row1(c, g_cb, g_centerterm, bid * 4 + wrp, -2.0f * EPSV, 0.0f);
        __threadfence();
        __syncwarp();
        if (lane == 0) atomicAdd(&g_cdone, 1);
    }

    // ---- own 16 feature rows: warp w converts rows base + w*4 .. +3 ----
    {
        int base = brow + (bid & 7) * 16 + wrp * 4;
        conv_rows4(f, g_fb, g_rowterm, base,
                   2.0f * EPSV, EPSV * EPSV * (float)DD);
        if (lane < 4) g_minmap[base + lane] = 0x7F800000;   // fmap(+inf)
        __threadfence();
        __syncwarp();
        if (lane == 0) atomicAdd(&g_gcnt[row_blk], 4);
    }

    // ---- wait for centers + this row group ----
    if (tid == 0) {
        volatile int* cd = &g_cdone;
        while (*cd < CC) __nanosleep(64);
        volatile int* gc = &g_gcnt[row_blk];
        while (*gc < BM) __nanosleep(64);
        __threadfence();
    }
    __syncthreads();

    // =========================== GEMM (R6 mainloop) ================================
    char* smb = sm_raw;
    const __nv_bfloat16* Ag = g_fb + (size_t)brow * DD;
    const __nv_bfloat16* Bg = g_cb + (size_t)bcol * DD;
    const uint32_t smem0 = (uint32_t)__cvta_generic_to_shared(smb);

    uint32_t aB[4], bB[4];
    {
        uint32_t hi16 = ((lane >> 4) & 1) << 4;
        #pragma unroll
        for (int mt = 0; mt < 4; mt++) {
            int r = wm * 64 + mt * 16 + (lane & 15);
            aB[mt] = ((uint32_t)(r * 128) | (uint32_t)((r & 7) << 4)) ^ hi16;
        }
        uint32_t hib = ((lane >> 3) & 1) << 4;
        #pragma unroll
        for (int p = 0; p < 4; p++) {
            int r = wn * 64 + p * 16 + (lane & 7) + ((lane & 16) >> 1);
            bB[p] = ((uint32_t)(r * 128) | (uint32_t)((r & 7) << 4)) ^ hib;
        }
    }

    float acc[4][8][4];
    #pragma unroll
    for (int mt = 0; mt < 4; mt++)
        #pragma unroll
        for (int nt = 0; nt < 8; nt++)
            #pragma unroll
            for (int j = 0; j < 4; j++) acc[mt][nt][j] = 0.f;

    auto stage = [&](int kt, int buf) {
        int k0 = kt * BK;
        char* As = smb + buf * STAGE_BYTES;
        char* Bs = As + A_BYTES;
        #pragma unroll
        for (int i = 0; i < 8; i++) {
            int idx = tid + i * NTHREADS;
            int r = idx >> 3, cc2 = idx & 7;
            cp16(As + swz(r, cc2 * 16), Ag + (size_t)r * DD + k0 + cc2 * 8);
        }
        #pragma unroll
        for (int i = 0; i < 8; i++) {
            int idx = tid + i * NTHREADS;
            int r = idx >> 3, cc2 = idx & 7;
            cp16(Bs + swz(r, cc2 * 16), Bg + (size_t)r * DD + k0 + cc2 * 8);
        }
        cp_commit();
    };

    stage(0, 0);
    stage(1, 1);

    for (int kt = 0; kt < NK; kt++) {
        if (kt < NK - 1) cp_wait<1>(); else cp_wait<0>();
        __syncthreads();

        const uint32_t a_base = smem0 + (uint32_t)((kt % STAGES) * STAGE_BYTES);
        const uint32_t b_base = a_base + A_BYTES;

        uint32_t a[4][4], b[4][4];
        #pragma unroll
        for (int mt = 0; mt < 4; mt++) ldm_x4(a[mt], a_base + aB[mt]);
        #pragma unroll
        for (int p = 0; p < 4; p++)  ldm_x4(b[p],  b_base + bB[p]);

        if (kt + 2 < NK) stage(kt + 2, (kt + 2) % STAGES);

        #pragma unroll
        for (int mt = 0; mt < 4; mt++)
            #pragma unroll
            for (int p = 0; p < 4; p++) {
                mma16816(acc[mt][2 * p],     a[mt], b[p][0], b[p][1]);
                mma16816(acc[mt][2 * p + 1], a[mt], b[p][2], b[p][3]);
            }

        #pragma unroll
        for (int ks = 1; ks < 4; ks++) {
            const uint32_t kx = (uint32_t)(ks * 32);
            #pragma unroll
            for (int mt = 0; mt < 4; mt++) ldm_x4(a[mt], a_base + (aB[mt] ^ kx));
            #pragma unroll
            for (int p = 0; p < 4; p++)  ldm_x4(b[p],  b_base + (bB[p] ^ kx));
            #pragma unroll
            for (int mt = 0; mt < 4; mt++)
                #pragma unroll
                for (int p = 0; p < 4; p++) {
                    mma16816(acc[mt][2 * p],     a[mt], b[p][0], b[p][1]);
                    mma16816(acc[mt][2 * p + 1], a[mt], b[p][2], b[p][3]);
                }
        }
    }

    // ---- fused min epilogue ----
    const float* ctp = g_centerterm + bcol + wn * 64 + (lane & 3) * 2;
    float ct0[8], ct1[8];
    #pragma unroll
    for (int nt = 0; nt < 8; nt++) {
        ct0[nt] = __ldg(ctp + nt * 8);
        ct1[nt] = __ldg(ctp + nt * 8 + 1);
    }
    #pragma unroll
    for (int mt = 0; mt < 4; mt++) {
        float m0 = 1e30f, m1 = 1e30f;
        #pragma unroll
        for (int nt = 0; nt < 8; nt++) {
            m0 = fminf(m0, fminf(fmaf(-2.f, acc[mt][nt][0], ct0[nt]),
                                 fmaf(-2.f, acc[mt][nt][1], ct1[nt])));
            m1 = fminf(m1, fminf(fmaf(-2.f, acc[mt][nt][2], ct0[nt]),
                                 fmaf(-2.f, acc[mt][nt][3], ct1[nt])));
        }
        #pragma unroll
        for (int off = 1; off < 4; off <<= 1) {
            m0 = fminf(m0, __shfl_xor_sync(0xffffffff, m0, off));
            m1 = fminf(m1, __shfl_xor_sync(0xffffffff, m1, off));
        }
        if ((lane & 3) == 0) {
            int r = brow + wm * 64 + mt * 16 + (lane >> 2);
            atomicMin(&g_minmap[r],     fmap(m0));
            atomicMin(&g_minmap[r + 8], fmap(m1));
        }
    }
}

// ---------------- masked reduction + dtype detect + counter reset -----------------
__global__ void __launch_bounds__(1024) reduce_final_kernel(
        const unsigned int* __restrict__ lw, float* __restrict__ out) {
    int tid = threadIdx.x;

    // labels dtype detect: odd 32-bit words in [0,16384) all zero iff int64
    __shared__ int s_odd;
    if (tid == 0) s_odd = 0;
    __syncthreads();
    unsigned int o = 0;
    #pragma unroll
    for (int j = 0; j < 8; j++) o |= lw[2 * (tid + j * 1024) + 1];
    if (o) atomicOr(&s_odd, 1);
    __syncthreads();
    bool lab64 = (s_odd == 0);
    const void* labels = (const void*)lw;

    float s = 0.f, c = 0.f;
    #pragma unroll
    for (int i = 0; i < 16; i++) {
        int row = tid + i * 1024;
        float m    = funmap(g_minmap[row]);
        float sq   = g_rowterm[row] + m;
        float dist = sqrtf(fmaxf(sq, 0.f));
        long long lab = lab64 ? ((const long long*)labels)[row]
                              : (long long)((const int*)labels)[row];
        if (lab == 0) { s += dist; c += 1.f; }
    }
    #pragma unroll
    for (int off = 16; off; off >>= 1) {
        s += __shfl_xor_sync(0xffffffff, s, off);
        c += __shfl_xor_sync(0xffffffff, c, off);
    }
    __shared__ float sh[2][32];
    int w = tid >> 5, l = tid & 31;
    if (l == 0) { sh[0][w] = s; sh[1][w] = c; }
    __syncthreads();
    if (w == 0) {
        float ts = sh[0][l], tc = sh[1][l];
        #pragma unroll
        for (int off = 16; off; off >>= 1) {
            ts += __shfl_xor_sync(0xffffffff, ts, off);
            tc += __shfl_xor_sync(0xffffffff, tc, off);
        }
        if (l == 0) out[0] = ts / (tc + DEN_EPS);
    }

    // reset producer/consumer counters for the next graph replay
    if (tid < 128) g_gcnt[tid] = 0;
    if (tid == 128) g_cdone = 0;
}

// ---------------- launch -------------------------------------------------------------
extern "C" void kernel_launch(void* const* d_in, const int* in_sizes, int n_in,
                              void* d_out, int out_size) {
    const float* features = (const float*)d_in[0];
    const void*  labels   = d_in[1];
    const float* centers  = (const float*)d_in[2];
    float* out = (float*)d_out;

    cudaFuncSetAttribute(fused_kernel,
                         cudaFuncAttributeMaxDynamicSharedMemorySize, GEMM_SMEM);

    fused_kernel<<<NGTILES, NTHREADS, GEMM_SMEM>>>(features, centers);
    reduce_final_kernel<<<1, 1024>>>((const unsigned int*)labels, out);
}

// round 10
// speedup vs baseline: 1.3705x; 1.0438x over previous
#include <cuda_runtime.h>
#include <cuda_bf16.h>
#include <cstdint>

// Problem constants
#define NN 16384
#define DD 1024
#define CC 1024
#define EPSV 1e-6f
#define DEN_EPS 1e-5f

// ---------------- device scratch (zero-init at module load; reset each replay) ----
__device__ __align__(1024) __nv_bfloat16 g_fb[NN * DD];   // features bf16 (32MB)
__device__ __align__(1024) __nv_bfloat16 g_cb[CC * DD];   // centers  bf16 ( 2MB)
__device__ float g_rowterm[NN];
__device__ float g_centerterm[CC];
__device__ int   g_minmap[NN];
__device__ int   g_gcnt[128];    // per-128-row-group feature counters
__device__ int   g_ccnt[8];      // per-128-center-column counters
__device__ int   g_odd_nonzero;  // labels are int32 iff set
__device__ float g_psum[16];
__device__ float g_pcnt[16];
__device__ int   g_rdone;        // reduce ticket

// ---------------- helpers ---------------------------------------------------------
__device__ __forceinline__ int fmap(float f) {
    int i = __float_as_int(f);
    return i >= 0 ? i : (i ^ 0x7FFFFFFF);
}
__device__ __forceinline__ float funmap(int i) {
    return __int_as_float(i >= 0 ? i : (i ^ 0x7FFFFFFF));
}

__device__ __forceinline__ void cp16(void* dst, const void* src) {
    unsigned d = (unsigned)__cvta_generic_to_shared(dst);
    asm volatile("cp.async.cg.shared.global [%0], [%1], 16;\n" :: "r"(d), "l"(src) : "memory");
}
__device__ __forceinline__ void cp_commit() {
    asm volatile("cp.async.commit_group;\n" ::: "memory");
}
template <int N>
__device__ __forceinline__ void cp_wait() {
    asm volatile("cp.async.wait_group %0;\n" :: "n"(N) : "memory");
}

__device__ __forceinline__ void ldm_x4(uint32_t* r, uint32_t saddr) {
    asm volatile("ldmatrix.sync.aligned.m8n8.x4.shared.b16 {%0,%1,%2,%3}, [%4];\n"
                 : "=r"(r[0]), "=r"(r[1]), "=r"(r[2]), "=r"(r[3]) : "r"(saddr));
}

__device__ __forceinline__ void mma16816(float* c, const uint32_t* a,
                                         uint32_t b0, uint32_t b1) {
    asm volatile(
        "mma.sync.aligned.m16n8k16.row.col.f32.bf16.bf16.f32 "
        "{%0,%1,%2,%3}, {%4,%5,%6,%7}, {%8,%9}, {%0,%1,%2,%3};\n"
        : "+f"(c[0]), "+f"(c[1]), "+f"(c[2]), "+f"(c[3])
        : "r"(a[0]), "r"(a[1]), "r"(a[2]), "r"(a[3]), "r"(b0), "r"(b1));
}

// ---------------- warp converts ONE row --------------------------------------------
__device__ __forceinline__ void conv_row1(const float* __restrict__ src,
                                          __nv_bfloat16* dst, float* term,
                                          int row, float coef, float add) {
    const int lane = threadIdx.x & 31;
    const float4* s4 = reinterpret_cast<const float4*>(src + (size_t)row * DD);
    uint2* d2 = reinterpret_cast<uint2*>(dst + (size_t)row * DD);
    float s = 0.f, s2 = 0.f;
    #pragma unroll
    for (int i = 0; i < 8; i++) {
        float4 v = s4[i * 32 + lane];
        __nv_bfloat162 lo = __floats2bfloat162_rn(v.x, v.y);
        __nv_bfloat162 hi = __floats2bfloat162_rn(v.z, v.w);
        uint2 packed;
        packed.x = *reinterpret_cast<uint32_t*>(&lo);
        packed.y = *reinterpret_cast<uint32_t*>(&hi);
        d2[i * 32 + lane] = packed;
        s  += v.x + v.y + v.z + v.w;
        s2 += v.x * v.x + v.y * v.y + v.z * v.z + v.w * v.w;
    }
    #pragma unroll
    for (int off = 16; off; off >>= 1) {
        s  += __shfl_xor_sync(0xffffffff, s,  off);
        s2 += __shfl_xor_sync(0xffffffff, s2, off);
    }
    if (lane == 0) term[row] = s2 + coef * s + add;
}

// ---------------- warp converts 4 consecutive rows (interleaved for MLP) -----------
__device__ __forceinline__ void conv_rows4(const float* __restrict__ src,
                                           __nv_bfloat16* dst, float* term,
                                           int row0, float coef, float add) {
    const int lane = threadIdx.x & 31;
    const float4* s4 = reinterpret_cast<const float4*>(src + (size_t)row0 * DD);
    uint2* d2 = reinterpret_cast<uint2*>(dst + (size_t)row0 * DD);

    float s[4]  = {0.f, 0.f, 0.f, 0.f};
    float s2[4] = {0.f, 0.f, 0.f, 0.f};
    #pragma unroll
    for (int i = 0; i < 8; i++) {
        float4 v[4];
        #pragma unroll
        for (int rr = 0; rr < 4; rr++) v[rr] = s4[rr * 256 + i * 32 + lane];
        #pragma unroll
        for (int rr = 0; rr < 4; rr++) {
            __nv_bfloat162 lo = __floats2bfloat162_rn(v[rr].x, v[rr].y);
            __nv_bfloat162 hi = __floats2bfloat162_rn(v[rr].z, v[rr].w);
            uint2 packed;
            packed.x = *reinterpret_cast<uint32_t*>(&lo);
            packed.y = *reinterpret_cast<uint32_t*>(&hi);
            d2[rr * 256 + i * 32 + lane] = packed;
            s[rr]  += v[rr].x + v[rr].y + v[rr].z + v[rr].w;
            s2[rr] += v[rr].x * v[rr].x + v[rr].y * v[rr].y
                    + v[rr].z * v[rr].z + v[rr].w * v[rr].w;
        }
    }
    #pragma unroll
    for (int rr = 0; rr < 4; rr++) {
        #pragma unroll
        for (int off = 16; off; off >>= 1) {
            s[rr]  += __shfl_xor_sync(0xffffffff, s[rr],  off);
            s2[rr] += __shfl_xor_sync(0xffffffff, s2[rr], off);
        }
        if (lane == 0) term[row0 + rr] = s2[rr] + coef * s[rr] + add;
    }
}

// ---------------- fused convert + GEMM + min epilogue ------------------------------
#define BM 128
#define BN 128
#define BK 64
#define NK (DD / BK)            // 16
#define A_BYTES (BM * BK * 2)   // 16384
#define B_BYTES (BN * BK * 2)   // 16384
#define STAGE_BYTES (A_BYTES + B_BYTES)
#define STAGES 3
#define GEMM_SMEM (STAGES * STAGE_BYTES + 16)
#define NTHREADS 128
#define NGTILES 1024

__device__ __forceinline__ uint32_t swz(int r, int kbyte) {
    return (uint32_t)(r * 128 + (((kbyte >> 4) ^ (r & 7)) << 4) + (kbyte & 15));
}

__global__ void __launch_bounds__(NTHREADS, 2) fused_kernel(
        const float* __restrict__ f, const float* __restrict__ c,
        const unsigned int* __restrict__ lw) {
    extern __shared__ char sm_raw[];
    const int tid  = threadIdx.x;
    const int lane = tid & 31;
    const int wrp  = tid >> 5;       // 0..3
    const int bid  = blockIdx.x;

    const int row_blk = bid >> 3;
    const int brow    = row_blk * BM;
    const int bcol    = (bid & 7) * BN;
    const int wm      = wrp >> 1;    // 0..1
    const int wn      = wrp & 1;     // 0..1

    // ---- centers: bids 0..255 convert 4 rows each (1 per warp), wave-1 resident ----
    if (bid < 256) {
        int crow = bid * 4 + wrp;
        conv_row1(c, g_cb, g_centerterm, crow, -2.0f * EPSV, 0.0f);
        __threadfence();
        __syncwarp();
        if (lane == 0) atomicAdd(&g_ccnt[crow >> 7], 1);
    } else if (bid < 320) {
        // labels dtype detect: 64 CTAs scan 256 words each (all 16384 words)
        int i = (bid - 256) * 256 + tid * 2 + 1;       // odd words
        if (lw[i] != 0u) atomicOr(&g_odd_nonzero, 1);
        if (lw[i + 128] != 0u) atomicOr(&g_odd_nonzero, 1);
    }

    // ---- own 16 feature rows: warp w converts rows base + w*4 .. +3 ----
    {
        int base = brow + (bid & 7) * 16 + wrp * 4;
        conv_rows4(f, g_fb, g_rowterm, base,
                   2.0f * EPSV, EPSV * EPSV * (float)DD);
        if (lane < 4) g_minmap[base + lane] = 0x7F800000;   // fmap(+inf)
        __threadfence();
        __syncwarp();
        if (lane == 0) atomicAdd(&g_gcnt[row_blk], 4);
    }

    // ---- wait for this tile's center column + feature row group ----
    if (tid == 0) {
        volatile int* cd = &g_ccnt[bid & 7];
        while (*cd < BN) __nanosleep(64);
        volatile int* gc = &g_gcnt[row_blk];
        while (*gc < BM) __nanosleep(64);
        __threadfence();
    }
    __syncthreads();

    // =========================== GEMM (R6 mainloop) =================================
    char* smb = sm_raw;
    const __nv_bfloat16* Ag = g_fb + (size_t)brow * DD;
    const __nv_bfloat16* Bg = g_cb + (size_t)bcol * DD;
    const uint32_t smem0 = (uint32_t)__cvta_generic_to_shared(smb);

    uint32_t aB[4], bB[4];
    {
        uint32_t hi16 = ((lane >> 4) & 1) << 4;
        #pragma unroll
        for (int mt = 0; mt < 4; mt++) {
            int r = wm * 64 + mt * 16 + (lane & 15);
            aB[mt] = ((uint32_t)(r * 128) | (uint32_t)((r & 7) << 4)) ^ hi16;
        }
        uint32_t hib = ((lane >> 3) & 1) << 4;
        #pragma unroll
        for (int p = 0; p < 4; p++) {
            int r = wn * 64 + p * 16 + (lane & 7) + ((lane & 16) >> 1);
            bB[p] = ((uint32_t)(r * 128) | (uint32_t)((r & 7) << 4)) ^ hib;
        }
    }

    float acc[4][8][4];
    #pragma unroll
    for (int mt = 0; mt < 4; mt++)
        #pragma unroll
        for (int nt = 0; nt < 8; nt++)
            #pragma unroll
            for (int j = 0; j < 4; j++) acc[mt][nt][j] = 0.f;

    auto stage = [&](int kt, int buf) {
        int k0 = kt * BK;
        char* As = smb + buf * STAGE_BYTES;
        char* Bs = As + A_BYTES;
        #pragma unroll
        for (int i = 0; i < 8; i++) {
            int idx = tid + i * NTHREADS;
            int r = idx >> 3, cc2 = idx & 7;
            cp16(As + swz(r, cc2 * 16), Ag + (size_t)r * DD + k0 + cc2 * 8);
        }
        #pragma unroll
        for (int i = 0; i < 8; i++) {
            int idx = tid + i * NTHREADS;
            int r = idx >> 3, cc2 = idx & 7;
            cp16(Bs + swz(r, cc2 * 16), Bg + (size_t)r * DD + k0 + cc2 * 8);
        }
        cp_commit();
    };

    stage(0, 0);
    stage(1, 1);

    for (int kt = 0; kt < NK; kt++) {
        if (kt < NK - 1) cp_wait<1>(); else cp_wait<0>();
        __syncthreads();

        const uint32_t a_base = smem0 + (uint32_t)((kt % STAGES) * STAGE_BYTES);
        const uint32_t b_base = a_base + A_BYTES;

        uint32_t a[4][4], b[4][4];
        #pragma unroll
        for (int mt = 0; mt < 4; mt++) ldm_x4(a[mt], a_base + aB[mt]);
        #pragma unroll
        for (int p = 0; p < 4; p++)  ldm_x4(b[p],  b_base + bB[p]);

        if (kt + 2 < NK) stage(kt + 2, (kt + 2) % STAGES);

        #pragma unroll
        for (int mt = 0; mt < 4; mt++)
            #pragma unroll
            for (int p = 0; p < 4; p++) {
                mma16816(acc[mt][2 * p],     a[mt], b[p][0], b[p][1]);
                mma16816(acc[mt][2 * p + 1], a[mt], b[p][2], b[p][3]);
            }

        #pragma unroll
        for (int ks = 1; ks < 4; ks++) {
            const uint32_t kx = (uint32_t)(ks * 32);
            #pragma unroll
            for (int mt = 0; mt < 4; mt++) ldm_x4(a[mt], a_base + (aB[mt] ^ kx));
            #pragma unroll
            for (int p = 0; p < 4; p++)  ldm_x4(b[p],  b_base + (bB[p] ^ kx));
            #pragma unroll
            for (int mt = 0; mt < 4; mt++)
                #pragma unroll
                for (int p = 0; p < 4; p++) {
                    mma16816(acc[mt][2 * p],     a[mt], b[p][0], b[p][1]);
                    mma16816(acc[mt][2 * p + 1], a[mt], b[p][2], b[p][3]);
                }
        }
    }

    // ---- fused min epilogue ----
    const float* ctp = g_centerterm + bcol + wn * 64 + (lane & 3) * 2;
    float ct0[8], ct1[8];
    #pragma unroll
    for (int nt = 0; nt < 8; nt++) {
        ct0[nt] = __ldg(ctp + nt * 8);
        ct1[nt] = __ldg(ctp + nt * 8 + 1);
    }
    #pragma unroll
    for (int mt = 0; mt < 4; mt++) {
        float m0 = 1e30f, m1 = 1e30f;
        #pragma unroll
        for (int nt = 0; nt < 8; nt++) {
            m0 = fminf(m0, fminf(fmaf(-2.f, acc[mt][nt][0], ct0[nt]),
                                 fmaf(-2.f, acc[mt][nt][1], ct1[nt])));
            m1 = fminf(m1, fminf(fmaf(-2.f, acc[mt][nt][2], ct0[nt]),
                                 fmaf(-2.f, acc[mt][nt][3], ct1[nt])));
        }
        #pragma unroll
        for (int off = 1; off < 4; off <<= 1) {
            m0 = fminf(m0, __shfl_xor_sync(0xffffffff, m0, off));
            m1 = fminf(m1, __shfl_xor_sync(0xffffffff, m1, off));
        }
        if ((lane & 3) == 0) {
            int r = brow + wm * 64 + mt * 16 + (lane >> 2);
            atomicMin(&g_minmap[r],     fmap(m0));
            atomicMin(&g_minmap[r + 8], fmap(m1));
        }
    }
}

// ---------------- multi-block masked reduction with last-block finish --------------
__global__ void __launch_bounds__(1024) reduce_kernel(
        const unsigned int* __restrict__ lw, float* __restrict__ out) {
    const int tid = threadIdx.x;
    const int row = blockIdx.x * 1024 + tid;
    const bool lab64 = (g_odd_nonzero == 0);
    const void* labels = (const void*)lw;

    float m    = funmap(g_minmap[row]);
    float sq   = g_rowterm[row] + m;
    float dist = sqrtf(fmaxf(sq, 0.f));
    long long lab = lab64 ? ((const long long*)labels)[row]
                          : (long long)((const int*)labels)[row];
    float s = (lab == 0) ? dist : 0.f;
    float c = (lab == 0) ? 1.f : 0.f;

    #pragma unroll
    for (int off = 16; off; off >>= 1) {
        s += __shfl_xor_sync(0xffffffff, s, off);
        c += __shfl_xor_sync(0xffffffff, c, off);
    }
    __shared__ float sh[2][32];
    const int w = tid >> 5, l = tid & 31;
    if (l == 0) { sh[0][w] = s; sh[1][w] = c; }
    __syncthreads();
    if (w == 0) {
        float ts = sh[0][l], tc = sh[1][l];
        #pragma unroll
        for (int off = 16; off; off >>= 1) {
            ts += __shfl_xor_sync(0xffffffff, ts, off);
            tc += __shfl_xor_sync(0xffffffff, tc, off);
        }
        if (l == 0) {
            g_psum[blockIdx.x] = ts;
            g_pcnt[blockIdx.x] = tc;
            __threadfence();
            int ticket = atomicAdd(&g_rdone, 1);
            if (ticket == 15) {
                // deterministic final sum in fixed order
                float S = 0.f, C = 0.f;
                #pragma unroll
                for (int i = 0; i < 16; i++) { S += g_psum[i]; C += g_pcnt[i]; }
                out[0] = S / (C + DEN_EPS);
                // reset all replay state
                #pragma unroll
                for (int i = 0; i < 128; i++) g_gcnt[i] = 0;
                #pragma unroll
                for (int i = 0; i < 8; i++) g_ccnt[i] = 0;
                g_odd_nonzero = 0;
                g_rdone = 0;
            }
        }
    }
}

// ---------------- launch --------------------------------------------------------------
extern "C" void kernel_launch(void* const* d_in, const int* in_sizes, int n_in,
                              void* d_out, int out_size) {
    const float* features = (const float*)d_in[0];
    const void*  labels   = d_in[1];
    const float* centers  = (const float*)d_in[2];
    float* out = (float*)d_out;

    cudaFuncSetAttribute(fused_kernel,
                         cudaFuncAttributeMaxDynamicSharedMemorySize, GEMM_SMEM);

    fused_kernel<<<NGTILES, NTHREADS, GEMM_SMEM>>>(
        features, centers, (const unsigned int*)labels);
    reduce_kernel<<<16, 1024>>>((const unsigned int*)labels, out);
}